// round 1
// baseline (speedup 1.0000x reference)
#include <cuda_runtime.h>

#define BATCH 2048
#define IN_SZ 40960
#define HID 256

// 40960 * 256 floats = 41.9 MB transposed feature-transformer weights.
__device__ float g_ftw_t[(size_t)IN_SZ * HID];

// ---------------------------------------------------------------------------
// Kernel 1: transpose ft_w [256, 40960] -> g_ftw_t [40960, 256]
// ---------------------------------------------------------------------------
__global__ __launch_bounds__(256) void transpose_ft(const float* __restrict__ ft_w) {
    __shared__ float tile[32][33];
    int x = blockIdx.x * 32 + threadIdx.x;   // input col  (feature index i)
    int y = blockIdx.y * 32 + threadIdx.y;   // input row  (hidden h), step 8
#pragma unroll
    for (int k = 0; k < 32; k += 8)
        tile[threadIdx.y + k][threadIdx.x] = ft_w[(size_t)(y + k) * IN_SZ + x];
    __syncthreads();
    int ox = blockIdx.y * 32 + threadIdx.x;  // output col (hidden h)
    int oy = blockIdx.x * 32 + threadIdx.y;  // output row (feature i)
#pragma unroll
    for (int k = 0; k < 32; k += 8)
        g_ftw_t[(size_t)(oy + k) * HID + ox] = tile[threadIdx.x][threadIdx.y + k];
}

// ---------------------------------------------------------------------------
// Kernel 2: one CTA (256 threads) per batch row.
//   - scan white/black one-hot rows (float4 streaming loads), collect indices
//   - gather + accumulate ftw_t rows, add bias, clip
//   - stm-ordered concat, fused 512->32->32->1 MLP
// ---------------------------------------------------------------------------
__global__ __launch_bounds__(256) void nnue_main(
    const float* __restrict__ white, const float* __restrict__ black,
    const float* __restrict__ stm,
    const float* __restrict__ ft_b,
    const float* __restrict__ l1w, const float* __restrict__ l1b,
    const float* __restrict__ l2w, const float* __restrict__ l2b,
    const float* __restrict__ l3w, const float* __restrict__ l3b,
    float* __restrict__ out)
{
    const int b   = blockIdx.x;
    const int tid = threadIdx.x;

    __shared__ int   widx[64], bidx[64];
    __shared__ int   cnt[2];
    __shared__ float hid[2 * HID];
    __shared__ float x1s[32];
    __shared__ float x2s[32];

    if (tid < 2) cnt[tid] = 0;
    __syncthreads();

    const float4* wr = reinterpret_cast<const float4*>(white + (size_t)b * IN_SZ);
    const float4* br = reinterpret_cast<const float4*>(black + (size_t)b * IN_SZ);

    // 40960 / 4 = 10240 float4 per row; 10240 / 256 = 40 iterations per perspective.
#pragma unroll 4
    for (int it = 0; it < 40; ++it) {
        int v = it * 256 + tid;
        float4 f = __ldcs(&wr[v]);
        if (f.x != 0.f || f.y != 0.f || f.z != 0.f || f.w != 0.f) {
            if (f.x != 0.f) { int p = atomicAdd(&cnt[0], 1); widx[p] = 4 * v + 0; }
            if (f.y != 0.f) { int p = atomicAdd(&cnt[0], 1); widx[p] = 4 * v + 1; }
            if (f.z != 0.f) { int p = atomicAdd(&cnt[0], 1); widx[p] = 4 * v + 2; }
            if (f.w != 0.f) { int p = atomicAdd(&cnt[0], 1); widx[p] = 4 * v + 3; }
        }
        float4 g = __ldcs(&br[v]);
        if (g.x != 0.f || g.y != 0.f || g.z != 0.f || g.w != 0.f) {
            if (g.x != 0.f) { int p = atomicAdd(&cnt[1], 1); bidx[p] = 4 * v + 0; }
            if (g.y != 0.f) { int p = atomicAdd(&cnt[1], 1); bidx[p] = 4 * v + 1; }
            if (g.z != 0.f) { int p = atomicAdd(&cnt[1], 1); bidx[p] = 4 * v + 2; }
            if (g.w != 0.f) { int p = atomicAdd(&cnt[1], 1); bidx[p] = 4 * v + 3; }
        }
    }
    __syncthreads();

    const int wc = cnt[0];
    const int bc = cnt[1];

    // Gather + accumulate: each of 256 threads owns one hidden unit.
    float bias = ft_b[tid];
    float aw = bias, ab = bias;
    for (int j = 0; j < wc; ++j) aw += g_ftw_t[(size_t)widx[j] * HID + tid];
    for (int j = 0; j < bc; ++j) ab += g_ftw_t[(size_t)bidx[j] * HID + tid];
    aw = fminf(fmaxf(aw, 0.f), 1.f);
    ab = fminf(fmaxf(ab, 0.f), 1.f);

    const bool s = (stm[b] != 0.f);
    hid[tid]       = s ? aw : ab;
    hid[HID + tid] = s ? ab : aw;
    __syncthreads();

    // Layer 1: 512 -> 32, 8 threads per output, shfl-reduce within groups of 8.
    {
        int k  = tid >> 3;       // output index 0..31
        int s8 = tid & 7;        // lane within group
        const float* w = l1w + k * 512;
        float p = 0.f;
#pragma unroll
        for (int j = s8; j < 512; j += 8) p += hid[j] * w[j];
        p += __shfl_down_sync(0xffffffffu, p, 4, 8);
        p += __shfl_down_sync(0xffffffffu, p, 2, 8);
        p += __shfl_down_sync(0xffffffffu, p, 1, 8);
        if (s8 == 0) x1s[k] = fminf(fmaxf(p + l1b[k], 0.f), 1.f);
    }
    __syncthreads();

    // Layer 2: 32 -> 32.
    if (tid < 32) {
        float p = l2b[tid];
        const float* w = l2w + tid * 32;
#pragma unroll
        for (int j = 0; j < 32; ++j) p += x1s[j] * w[j];
        x2s[tid] = fminf(fmaxf(p, 0.f), 1.f);
    }
    __syncwarp(0xffffffffu);

    // Layer 3: 32 -> 1 (warp reduce, first warp only).
    if (tid < 32) {
        float p = x2s[tid] * l3w[tid];
        p += __shfl_down_sync(0xffffffffu, p, 16);
        p += __shfl_down_sync(0xffffffffu, p, 8);
        p += __shfl_down_sync(0xffffffffu, p, 4);
        p += __shfl_down_sync(0xffffffffu, p, 2);
        p += __shfl_down_sync(0xffffffffu, p, 1);
        if (tid == 0) out[b] = p + l3b[0];
    }
}

// ---------------------------------------------------------------------------
// Launch
// ---------------------------------------------------------------------------
extern "C" void kernel_launch(void* const* d_in, const int* in_sizes, int n_in,
                              void* d_out, int out_size) {
    const float* white = (const float*)d_in[0];
    const float* black = (const float*)d_in[1];
    const float* stm   = (const float*)d_in[2];
    const float* ft_w  = (const float*)d_in[3];
    const float* ft_b  = (const float*)d_in[4];
    const float* l1w   = (const float*)d_in[5];
    const float* l1b   = (const float*)d_in[6];
    const float* l2w   = (const float*)d_in[7];
    const float* l2b   = (const float*)d_in[8];
    const float* l3w   = (const float*)d_in[9];
    const float* l3b   = (const float*)d_in[10];
    float* out = (float*)d_out;

    dim3 tb(32, 8);
    dim3 tg(IN_SZ / 32, HID / 32);
    transpose_ft<<<tg, tb>>>(ft_w);

    nnue_main<<<BATCH, 256>>>(white, black, stm, ft_b,
                              l1w, l1b, l2w, l2b, l3w, l3b, out);
}

// round 2
// speedup vs baseline: 1.0109x; 1.0109x over previous
#include <cuda_runtime.h>

#define BATCH 2048
#define IN_SZ 40960
#define HID 256
#define NF4 (BATCH * (IN_SZ / 4))      // float4 per one-hot array = 20,971,520
#define SCAN_CTAS 2048
#define SCAN_THREADS 256
#define SCAN_T (SCAN_CTAS * SCAN_THREADS)   // 524288 threads
#define SCAN_ITERS (NF4 / SCAN_T)           // 40 per perspective

// Scratch (allocation-free: __device__ globals)
__device__ float g_ftw_t[(size_t)IN_SZ * HID];   // 41.9 MB transposed ft weights
__device__ int   g_cnt[2][BATCH];
__device__ int   g_idx[2][BATCH][32];

// ---------------------------------------------------------------------------
// Kernel 0: clear per-row counters
// ---------------------------------------------------------------------------
__global__ void clear_cnt() {
    int t = blockIdx.x * blockDim.x + threadIdx.x;
    if (t < 2 * BATCH) ((int*)g_cnt)[t] = 0;
}

// ---------------------------------------------------------------------------
// Kernel 1: pure streaming scan of both one-hot arrays -> sparse index lists
// ---------------------------------------------------------------------------
__global__ __launch_bounds__(SCAN_THREADS) void scan(
    const float* __restrict__ white, const float* __restrict__ black)
{
    const int t = blockIdx.x * SCAN_THREADS + threadIdx.x;

#pragma unroll
    for (int p = 0; p < 2; ++p) {
        const float4* src = reinterpret_cast<const float4*>(p ? black : white);
        for (int it = 0; it < SCAN_ITERS; it += 8) {
            float4 f[8];
#pragma unroll
            for (int u = 0; u < 8; ++u)
                f[u] = __ldcs(&src[t + (size_t)(it + u) * SCAN_T]);
#pragma unroll
            for (int u = 0; u < 8; ++u) {
                if (f[u].x != 0.f || f[u].y != 0.f || f[u].z != 0.f || f[u].w != 0.f) {
                    int v    = t + (it + u) * SCAN_T;
                    int row  = v / (IN_SZ / 4);
                    int base = (v - row * (IN_SZ / 4)) * 4;
                    if (f[u].x != 0.f) { int s = atomicAdd(&g_cnt[p][row], 1); g_idx[p][row][s] = base + 0; }
                    if (f[u].y != 0.f) { int s = atomicAdd(&g_cnt[p][row], 1); g_idx[p][row][s] = base + 1; }
                    if (f[u].z != 0.f) { int s = atomicAdd(&g_cnt[p][row], 1); g_idx[p][row][s] = base + 2; }
                    if (f[u].w != 0.f) { int s = atomicAdd(&g_cnt[p][row], 1); g_idx[p][row][s] = base + 3; }
                }
            }
        }
    }
}

// ---------------------------------------------------------------------------
// Kernel 2: transpose ft_w [256, 40960] -> g_ftw_t [40960, 256]
// (runs AFTER scan so g_ftw_t stays hot in L2 for the gather)
// ---------------------------------------------------------------------------
__global__ __launch_bounds__(256) void transpose_ft(const float* __restrict__ ft_w) {
    __shared__ float tile[32][33];
    int x = blockIdx.x * 32 + threadIdx.x;
    int y = blockIdx.y * 32 + threadIdx.y;
#pragma unroll
    for (int k = 0; k < 32; k += 8)
        tile[threadIdx.y + k][threadIdx.x] = ft_w[(size_t)(y + k) * IN_SZ + x];
    __syncthreads();
    int ox = blockIdx.y * 32 + threadIdx.x;
    int oy = blockIdx.x * 32 + threadIdx.y;
#pragma unroll
    for (int k = 0; k < 32; k += 8)
        g_ftw_t[(size_t)(oy + k) * HID + ox] = tile[threadIdx.x][threadIdx.y + k];
}

// ---------------------------------------------------------------------------
// Kernel 3: gather + fused MLP. One CTA (256 threads) per batch row.
// ---------------------------------------------------------------------------
__global__ __launch_bounds__(256) void gather_mlp(
    const float* __restrict__ stm,
    const float* __restrict__ ft_b,
    const float* __restrict__ l1w, const float* __restrict__ l1b,
    const float* __restrict__ l2w, const float* __restrict__ l2b,
    const float* __restrict__ l3w, const float* __restrict__ l3b,
    float* __restrict__ out)
{
    const int b   = blockIdx.x;
    const int tid = threadIdx.x;

    __shared__ int   widx[32], bidx[32];
    __shared__ float hid[2 * HID];
    __shared__ float x1s[32];
    __shared__ float x2s[32];

    if (tid < 32)      widx[tid]      = g_idx[0][b][tid];
    else if (tid < 64) bidx[tid - 32] = g_idx[1][b][tid - 32];
    __syncthreads();

    const int wc = g_cnt[0][b];
    const int bc = g_cnt[1][b];

    float bias = ft_b[tid];
    float aw = bias, ab = bias;
    for (int j = 0; j < wc; ++j) aw += g_ftw_t[(size_t)widx[j] * HID + tid];
    for (int j = 0; j < bc; ++j) ab += g_ftw_t[(size_t)bidx[j] * HID + tid];
    aw = fminf(fmaxf(aw, 0.f), 1.f);
    ab = fminf(fmaxf(ab, 0.f), 1.f);

    const bool s = (stm[b] != 0.f);
    hid[tid]       = s ? aw : ab;
    hid[HID + tid] = s ? ab : aw;
    __syncthreads();

    // Layer 1: 512 -> 32, 8 threads per output
    {
        int k  = tid >> 3;
        int s8 = tid & 7;
        const float* w = l1w + k * 512;
        float p = 0.f;
#pragma unroll
        for (int j = s8; j < 512; j += 8) p += hid[j] * w[j];
        p += __shfl_down_sync(0xffffffffu, p, 4, 8);
        p += __shfl_down_sync(0xffffffffu, p, 2, 8);
        p += __shfl_down_sync(0xffffffffu, p, 1, 8);
        if (s8 == 0) x1s[k] = fminf(fmaxf(p + l1b[k], 0.f), 1.f);
    }
    __syncthreads();

    // Layer 2: 32 -> 32
    if (tid < 32) {
        float p = l2b[tid];
        const float* w = l2w + tid * 32;
#pragma unroll
        for (int j = 0; j < 32; ++j) p += x1s[j] * w[j];
        x2s[tid] = fminf(fmaxf(p, 0.f), 1.f);
    }
    __syncwarp(0xffffffffu);

    // Layer 3: 32 -> 1
    if (tid < 32) {
        float p = x2s[tid] * l3w[tid];
        p += __shfl_down_sync(0xffffffffu, p, 16);
        p += __shfl_down_sync(0xffffffffu, p, 8);
        p += __shfl_down_sync(0xffffffffu, p, 4);
        p += __shfl_down_sync(0xffffffffu, p, 2);
        p += __shfl_down_sync(0xffffffffu, p, 1);
        if (tid == 0) out[b] = p + l3b[0];
    }
}

// ---------------------------------------------------------------------------
// Launch
// ---------------------------------------------------------------------------
extern "C" void kernel_launch(void* const* d_in, const int* in_sizes, int n_in,
                              void* d_out, int out_size) {
    const float* white = (const float*)d_in[0];
    const float* black = (const float*)d_in[1];
    const float* stm   = (const float*)d_in[2];
    const float* ft_w  = (const float*)d_in[3];
    const float* ft_b  = (const float*)d_in[4];
    const float* l1w   = (const float*)d_in[5];
    const float* l1b   = (const float*)d_in[6];
    const float* l2w   = (const float*)d_in[7];
    const float* l2b   = (const float*)d_in[8];
    const float* l3w   = (const float*)d_in[9];
    const float* l3b   = (const float*)d_in[10];
    float* out = (float*)d_out;

    clear_cnt<<<8, 512>>>();
    scan<<<SCAN_CTAS, SCAN_THREADS>>>(white, black);

    dim3 tb(32, 8);
    dim3 tg(IN_SZ / 32, HID / 32);
    transpose_ft<<<tg, tb>>>(ft_w);

    gather_mlp<<<BATCH, 256>>>(stm, ft_b, l1w, l1b, l2w, l2b, l3w, l3b, out);
}

// round 3
// speedup vs baseline: 1.0397x; 1.0285x over previous
#include <cuda_runtime.h>

#define BATCH 2048
#define IN_SZ 40960
#define HID 256
#define NF4 (BATCH * (IN_SZ / 4))
#define SCAN_CTAS 2048
#define SCAN_THREADS 256
#define SCAN_T (SCAN_CTAS * SCAN_THREADS)
#define SCAN_ITERS (NF4 / SCAN_T)

__device__ float g_ftw_t[(size_t)IN_SZ * HID];   // 41.9 MB transposed weights
__device__ int   g_cnt[2][BATCH];
__device__ int   g_idx[2][BATCH][32];

// ---------------------------------------------------------------------------
// Kernel 0: clear per-row counters
// ---------------------------------------------------------------------------
__global__ void clear_cnt() {
    int t = blockIdx.x * blockDim.x + threadIdx.x;
    if (t < 2 * BATCH) ((int*)g_cnt)[t] = 0;
}

// ---------------------------------------------------------------------------
// Kernel 1: streaming scan of one-hot arrays -> sparse index lists
// ---------------------------------------------------------------------------
__global__ __launch_bounds__(SCAN_THREADS) void scan(
    const float* __restrict__ white, const float* __restrict__ black)
{
    const int t = blockIdx.x * SCAN_THREADS + threadIdx.x;

#pragma unroll
    for (int p = 0; p < 2; ++p) {
        const float4* src = reinterpret_cast<const float4*>(p ? black : white);
        for (int it = 0; it < SCAN_ITERS; it += 8) {
            float4 f[8];
#pragma unroll
            for (int u = 0; u < 8; ++u)
                f[u] = __ldcs(&src[t + (size_t)(it + u) * SCAN_T]);
#pragma unroll
            for (int u = 0; u < 8; ++u) {
                if (f[u].x != 0.f || f[u].y != 0.f || f[u].z != 0.f || f[u].w != 0.f) {
                    int v    = t + (it + u) * SCAN_T;
                    int row  = v / (IN_SZ / 4);
                    int base = (v - row * (IN_SZ / 4)) * 4;
                    if (f[u].x != 0.f) { int s = atomicAdd(&g_cnt[p][row], 1); g_idx[p][row][s] = base + 0; }
                    if (f[u].y != 0.f) { int s = atomicAdd(&g_cnt[p][row], 1); g_idx[p][row][s] = base + 1; }
                    if (f[u].z != 0.f) { int s = atomicAdd(&g_cnt[p][row], 1); g_idx[p][row][s] = base + 2; }
                    if (f[u].w != 0.f) { int s = atomicAdd(&g_cnt[p][row], 1); g_idx[p][row][s] = base + 3; }
                }
            }
        }
    }
}

// ---------------------------------------------------------------------------
// Kernel 2: transpose ft_w [256, 40960] -> g_ftw_t [40960, 256]
// (after scan, so it lands hot in L2 for the gather)
// ---------------------------------------------------------------------------
__global__ __launch_bounds__(256) void transpose_ft(const float* __restrict__ ft_w) {
    __shared__ float tile[32][33];
    int x = blockIdx.x * 32 + threadIdx.x;
    int y = blockIdx.y * 32 + threadIdx.y;
#pragma unroll
    for (int k = 0; k < 32; k += 8)
        tile[threadIdx.y + k][threadIdx.x] = ft_w[(size_t)(y + k) * IN_SZ + x];
    __syncthreads();
    int ox = blockIdx.y * 32 + threadIdx.x;
    int oy = blockIdx.x * 32 + threadIdx.y;
#pragma unroll
    for (int k = 0; k < 32; k += 8)
        g_ftw_t[(size_t)(oy + k) * HID + ox] = tile[threadIdx.x][threadIdx.y + k];
}

// ---------------------------------------------------------------------------
// Kernel 3: float4-vectorized gather + fused MLP. One CTA per batch row.
//   thread = (c = tid&63 float4-column, fg = tid>>6 feature group of 4)
// ---------------------------------------------------------------------------
__global__ __launch_bounds__(256) void gather_mlp(
    const float* __restrict__ stm,
    const float* __restrict__ ft_b,
    const float* __restrict__ l1w, const float* __restrict__ l1b,
    const float* __restrict__ l2w, const float* __restrict__ l2b,
    const float* __restrict__ l3w, const float* __restrict__ l3b,
    float* __restrict__ out)
{
    const int b   = blockIdx.x;
    const int tid = threadIdx.x;

    __shared__ int    widx[32], bidx[32];
    __shared__ float4 red[2][4][64];   // [persp][fgroup][float4 col]  8 KB
    __shared__ float  hid[2 * HID];
    __shared__ float  x1s[32];
    __shared__ float  x2s[32];

    if (tid < 32)      widx[tid]      = g_idx[0][b][tid];
    else if (tid < 64) bidx[tid - 32] = g_idx[1][b][tid - 32];
    __syncthreads();

    const int wc = g_cnt[0][b];
    const int bc = g_cnt[1][b];

    const int c  = tid & 63;
    const int fg = tid >> 6;
    const float4* __restrict__ ftw4 = reinterpret_cast<const float4*>(g_ftw_t);

    float4 aw = make_float4(0.f, 0.f, 0.f, 0.f);
    float4 ab = make_float4(0.f, 0.f, 0.f, 0.f);
#pragma unroll 4
    for (int j = fg; j < wc; j += 4) {
        float4 v = ftw4[(size_t)widx[j] * 64 + c];
        aw.x += v.x; aw.y += v.y; aw.z += v.z; aw.w += v.w;
    }
#pragma unroll 4
    for (int j = fg; j < bc; j += 4) {
        float4 v = ftw4[(size_t)bidx[j] * 64 + c];
        ab.x += v.x; ab.y += v.y; ab.z += v.z; ab.w += v.w;
    }
    red[0][fg][c] = aw;
    red[1][fg][c] = ab;
    __syncthreads();

    const bool s = (stm[b] != 0.f);

    // 128 threads: finish reduction, add bias, clip, stm-ordered store
    if (tid < 128) {
        int p  = tid >> 6;      // perspective: 0 = white, 1 = black
        int cc = tid & 63;
        float4 v0 = red[p][0][cc], v1 = red[p][1][cc];
        float4 v2 = red[p][2][cc], v3 = red[p][3][cc];
        float4 bi = reinterpret_cast<const float4*>(ft_b)[cc];
        float4 r;
        r.x = fminf(fmaxf(v0.x + v1.x + v2.x + v3.x + bi.x, 0.f), 1.f);
        r.y = fminf(fmaxf(v0.y + v1.y + v2.y + v3.y + bi.y, 0.f), 1.f);
        r.z = fminf(fmaxf(v0.z + v1.z + v2.z + v3.z + bi.z, 0.f), 1.f);
        r.w = fminf(fmaxf(v0.w + v1.w + v2.w + v3.w + bi.w, 0.f), 1.f);
        int half = ((p == 0) == s) ? 0 : 1;   // stm: white first, else black first
        reinterpret_cast<float4*>(hid)[half * 64 + cc] = r;
    }
    __syncthreads();

    // Layer 1: 512 -> 32, 8 threads per output
    {
        int k  = tid >> 3;
        int s8 = tid & 7;
        const float* w = l1w + k * 512;
        float p = 0.f;
#pragma unroll
        for (int j = s8; j < 512; j += 8) p += hid[j] * w[j];
        p += __shfl_down_sync(0xffffffffu, p, 4, 8);
        p += __shfl_down_sync(0xffffffffu, p, 2, 8);
        p += __shfl_down_sync(0xffffffffu, p, 1, 8);
        if (s8 == 0) x1s[k] = fminf(fmaxf(p + l1b[k], 0.f), 1.f);
    }
    __syncthreads();

    // Layer 2: 32 -> 32
    if (tid < 32) {
        float p = l2b[tid];
        const float* w = l2w + tid * 32;
#pragma unroll
        for (int j = 0; j < 32; ++j) p += x1s[j] * w[j];
        x2s[tid] = fminf(fmaxf(p, 0.f), 1.f);
    }
    __syncwarp(0xffffffffu);

    // Layer 3: 32 -> 1
    if (tid < 32) {
        float p = x2s[tid] * l3w[tid];
        p += __shfl_down_sync(0xffffffffu, p, 16);
        p += __shfl_down_sync(0xffffffffu, p, 8);
        p += __shfl_down_sync(0xffffffffu, p, 4);
        p += __shfl_down_sync(0xffffffffu, p, 2);
        p += __shfl_down_sync(0xffffffffu, p, 1);
        if (tid == 0) out[b] = p + l3b[0];
    }
}

// ---------------------------------------------------------------------------
// Launch
// ---------------------------------------------------------------------------
extern "C" void kernel_launch(void* const* d_in, const int* in_sizes, int n_in,
                              void* d_out, int out_size) {
    const float* white = (const float*)d_in[0];
    const float* black = (const float*)d_in[1];
    const float* stm   = (const float*)d_in[2];
    const float* ft_w  = (const float*)d_in[3];
    const float* ft_b  = (const float*)d_in[4];
    const float* l1w   = (const float*)d_in[5];
    const float* l1b   = (const float*)d_in[6];
    const float* l2w   = (const float*)d_in[7];
    const float* l2b   = (const float*)d_in[8];
    const float* l3w   = (const float*)d_in[9];
    const float* l3b   = (const float*)d_in[10];
    float* out = (float*)d_out;

    clear_cnt<<<8, 512>>>();
    scan<<<SCAN_CTAS, SCAN_THREADS>>>(white, black);

    dim3 tb(32, 8);
    dim3 tg(IN_SZ / 32, HID / 32);
    transpose_ft<<<tg, tb>>>(ft_w);

    gather_mlp<<<BATCH, 256>>>(stm, ft_b, l1w, l1b, l2w, l2b, l3w, l3b, out);
}